// round 5
// baseline (speedup 1.0000x reference)
#include <cuda_runtime.h>
#include <cuda_bf16.h>
#include <cstdint>

// Problem constants (fixed shapes from setup_inputs)
#define B_DIM 8
#define T_DIM 4096
#define D_DIM 1024
#define K_FFT 64
#define F_DIM (K_FFT / 2 + 1)        // 33

#define NUM_CONV 128                 // B * D/64
#define NUM_ZERO 152                 // one per SM (GB300: 152 SMs) -> every TMA engine driven
#define GRID_TOTAL (NUM_CONV + NUM_ZERO)

#define ZCHUNK        32768                         // 32 KB SMEM zero buffer / bulk-store size
#define BYTES_PER_B   ((long long)(T_DIM - K_FFT) * D_DIM * 4)  // 16515072
#define CHUNKS_PER_B  504                           // 16515072 / 32768 (exact)
#define TOTAL_CHUNKS  (CHUNKS_PER_B * B_DIM)        // 4032
#define BATCH_STRIDE_BYTES ((long long)T_DIM * D_DIM * 4)

// Shared pool, aliased per path:
//   conv: g_sh[2112] | tab[64] | w_sh[4096] | f_sh[4160]  = 10432 floats (40.75 KB)
//   zero: first 8192 floats = 32 KB zero buffer for TMA bulk stores
#define SM_POOL_FLOATS 10432
#define G_OFF   0
#define TAB_OFF 2112
#define W_OFF   2176
#define F_OFF   6272

__global__ void __launch_bounds__(256, 4) spectral_fused_kernel(
    const float* __restrict__ x, const float* __restrict__ mask,
    const float* __restrict__ mix_w, float* __restrict__ out)
{
    __shared__ float pool[SM_POOL_FLOATS];

    const int bid = blockIdx.x;
    const int tid = threadIdx.x;

    if (bid >= NUM_CONV) {
        // ---- zero path: TMA bulk stores of a zeroed SMEM buffer ----
        float4* s4 = (float4*)pool;                  // 2048 float4 = 32 KB
        const float4 z = make_float4(0.f, 0.f, 0.f, 0.f);
        #pragma unroll
        for (int i = 0; i < 8; i++)
            s4[tid + i * 256] = z;
        __syncthreads();
        asm volatile("fence.proxy.async.shared::cta;" ::: "memory");

        if (tid == 0) {
            uint32_t saddr = (uint32_t)__cvta_generic_to_shared(pool);
            const int zb = bid - NUM_CONV;
            for (int c = zb; c < TOTAL_CHUNKS; c += NUM_ZERO) {
                int b   = c / CHUNKS_PER_B;          // const-div -> mulhi
                int off = c - b * CHUNKS_PER_B;
                char* dst = (char*)out + (long long)b * BATCH_STRIDE_BYTES
                                       + (long long)off * ZCHUNK;
                asm volatile(
                    "cp.async.bulk.global.shared::cta.bulk_group [%0], [%1], %2;"
                    :: "l"(dst), "r"(saddr), "n"(ZCHUNK) : "memory");
            }
            asm volatile("cp.async.bulk.commit_group;" ::: "memory");
            asm volatile("cp.async.bulk.wait_group 0;" ::: "memory");
        }
        return;
    }

    // ---- conv path (unchanged from R4): filter build + register conv ----
    float* g_sh = pool + G_OFF;     // [dl][f], 64*33
    float* tab  = pool + TAB_OFF;   // cos(2*pi*n/64)
    float* w_sh = pool + W_OFF;     // window [k][dl]
    float* f_sh = pool + F_OFF;     // filter [dl][n], pad 65

    const int b  = bid >> 4;          // 0..7
    const int d0 = (bid & 15) * 64;   // channel tile base

    const float* mrow = mask + (long long)d0 * F_DIM;
    for (int idx = tid; idx < 64 * F_DIM; idx += 256)
        g_sh[idx] = 1.0f / (1.0f + expf(-mrow[idx]));
    if (tid < K_FFT)
        tab[tid] = cospif((float)tid * (1.0f / 32.0f));   // exact twiddles

    const float* xb = x + ((long long)b * T_DIM + (T_DIM - K_FFT)) * D_DIM + d0;
    #pragma unroll
    for (int i = 0; i < 16; i++) {
        int idx = tid + i * 256;
        int k = idx >> 6, dl = idx & 63;
        w_sh[idx] = xb[(long long)k * D_DIM + dl];
    }
    __syncthreads();

    // f[dl][n] = mix_w/64 * ( g0 + 2*sum_{f=1..31} g_f cos(2 pi f n/64) + g32*(-1)^n )
    #pragma unroll
    for (int i = 0; i < 16; i++) {
        int idx = tid + i * 256;
        int dl = idx >> 6, n = idx & 63;
        const float* gd = g_sh + dl * F_DIM;
        float s = gd[0] + gd[32] * tab[(32 * n) & 63];
        #pragma unroll
        for (int f = 1; f < 32; f++)
            s += 2.0f * gd[f] * tab[(f * n) & 63];
        f_sh[dl * 65 + n] = s * (1.0f / 64.0f) * mix_w[d0 + dl];
    }
    __syncthreads();

    const int dl = tid & 63;
    const int t0 = (tid >> 6) * 16;

    // Pre-rotated filter in registers: fr[i] = f[(t0+i)&63]
    float fr[K_FFT];
    #pragma unroll
    for (int i = 0; i < K_FFT; i++)
        fr[i] = f_sh[dl * 65 + ((t0 + i) & 63)];

    float acc[16];
    #pragma unroll
    for (int j = 0; j < 16; j++) acc[j] = 0.0f;

    #pragma unroll
    for (int k = 0; k < K_FFT; k++) {
        float wv = w_sh[k * 64 + dl];
        #pragma unroll
        for (int j = 0; j < 16; j++)
            acc[j] += wv * fr[(j - k + K_FFT) & 63];   // compile-time reg index
    }

    float* ob = out + ((long long)b * T_DIM + (T_DIM - K_FFT)) * D_DIM + d0;
    #pragma unroll
    for (int j = 0; j < 16; j++)
        ob[(long long)(t0 + j) * D_DIM + dl] = acc[j];
}

// ---------------------------------------------------------------------------
// Launch: one kernel, one graph node.
// ---------------------------------------------------------------------------
extern "C" void kernel_launch(void* const* d_in, const int* in_sizes, int n_in,
                              void* d_out, int out_size)
{
    const float* x     = (const float*)d_in[0];   // (B, T, D) fp32
    const float* mask  = (const float*)d_in[1];   // (D, 33)   fp32
    const float* mix_w = (const float*)d_in[2];   // (D,)      fp32
    float* out = (float*)d_out;                   // (B, T, D) fp32

    spectral_fused_kernel<<<GRID_TOTAL, 256>>>(x, mask, mix_w, out);
}

// round 6
// speedup vs baseline: 1.1918x; 1.1918x over previous
#include <cuda_runtime.h>
#include <cuda_bf16.h>
#include <cstdint>

// Problem constants (fixed shapes from setup_inputs)
#define B_DIM 8
#define T_DIM 4096
#define D_DIM 1024
#define K_FFT 64
#define F_DIM (K_FFT / 2 + 1)        // 33

#define NUM_CONV 128                            // B * D/64
#define GRID_TOTAL  592                         // 4 blocks/SM * 148 SMs: one exact wave
#define NUM_ZERO (GRID_TOTAL - NUM_CONV)        // 464

// Zero region: rows [0, T-K) of each batch = 16,515,072 B/batch, 132,120,576 B total.
#define ZCHUNK        32768                     // 32 KB TMA bulk-store size
#define CHUNKS_PER_B  504                       // 16515072 / 32768 exact
#define TOTAL_CHUNKS  (CHUNKS_PER_B * B_DIM)    // 4032
#define TMA_CHUNKS_PER_BLOCK 4
#define NTMA          (NUM_ZERO * TMA_CHUNKS_PER_BLOCK)   // 1856 chunks via TMA (46%)

#define Z4_PER_B      ((T_DIM - K_FFT) * D_DIM / 4)       // 1,032,192 float4 per batch
#define Z4_TOTAL      (Z4_PER_B * B_DIM)                  // 8,257,536
#define STG_START4    (NTMA * (ZCHUNK / 16))              // 3,801,088 (chunks 1856.. via STG)
#define BSTRIDE4      (T_DIM * D_DIM / 4)                 // 4,194,304
#define BATCH_STRIDE_BYTES ((long long)T_DIM * D_DIM * 4)

// Shared pool, aliased per path:
//   conv: g_sh[2112] | tab[64] | w_sh[4096] | f_sh[4160] = 10432 floats (40.75 KB)
//   zero: first 8192 floats = 32 KB zero buffer for TMA bulk stores
#define SM_POOL_FLOATS 10432
#define G_OFF   0
#define TAB_OFF 2112
#define W_OFF   2176
#define F_OFF   6272

__global__ void __launch_bounds__(256, 4) spectral_fused_kernel(
    const float* __restrict__ x, const float* __restrict__ mask,
    const float* __restrict__ mix_w, float* __restrict__ out)
{
    __shared__ float pool[SM_POOL_FLOATS];

    const int bid = blockIdx.x;
    const int tid = threadIdx.x;

    if (bid >= NUM_CONV) {
        // ================= zero path: hybrid TMA + STG =================
        const int zb = bid - NUM_CONV;

        // Zero the 32 KB SMEM buffer.
        float4* s4 = (float4*)pool;
        const float4 z = make_float4(0.f, 0.f, 0.f, 0.f);
        #pragma unroll
        for (int i = 0; i < 8; i++)
            s4[tid + i * 256] = z;
        __syncthreads();
        asm volatile("fence.proxy.async.shared::cta;" ::: "memory");

        // (a) TMA share: 4 chunks of 32 KB per block, async (drains while we STG).
        if (tid == 0) {
            uint32_t saddr = (uint32_t)__cvta_generic_to_shared(pool);
            #pragma unroll
            for (int j = 0; j < TMA_CHUNKS_PER_BLOCK; j++) {
                int c   = zb * TMA_CHUNKS_PER_BLOCK + j;
                int b   = c / CHUNKS_PER_B;
                int off = c - b * CHUNKS_PER_B;
                char* dst = (char*)out + (long long)b * BATCH_STRIDE_BYTES
                                       + (long long)off * ZCHUNK;
                asm volatile(
                    "cp.async.bulk.global.shared::cta.bulk_group [%0], [%1], %2;"
                    :: "l"(dst), "r"(saddr), "n"(ZCHUNK) : "memory");
            }
            asm volatile("cp.async.bulk.commit_group;" ::: "memory");
        }

        // (b) STG share: float4 grid-stride over the remaining 54% of the region.
        {
            const int stride = NUM_ZERO * 256;             // 118,784
            for (int i = STG_START4 + zb * 256 + tid; i < Z4_TOTAL; i += stride) {
                int b   = i / Z4_PER_B;                    // const-div -> mulhi
                int off = i - b * Z4_PER_B;
                ((float4*)out)[b * BSTRIDE4 + off] = z;
            }
        }

        // SMEM buffer must stay alive until TMA reads finish.
        if (tid == 0)
            asm volatile("cp.async.bulk.wait_group 0;" ::: "memory");
        return;
    }

    // ================= conv path (unchanged from R4) =================
    float* g_sh = pool + G_OFF;     // sigmoid(mask) tile [dl][f]
    float* tab  = pool + TAB_OFF;   // cos(2*pi*n/64)
    float* w_sh = pool + W_OFF;     // window [k][dl]
    float* f_sh = pool + F_OFF;     // filter [dl][n], pad 65

    const int b  = bid >> 4;          // 0..7
    const int d0 = (bid & 15) * 64;   // channel tile base

    const float* mrow = mask + (long long)d0 * F_DIM;
    for (int idx = tid; idx < 64 * F_DIM; idx += 256)
        g_sh[idx] = 1.0f / (1.0f + expf(-mrow[idx]));
    if (tid < K_FFT)
        tab[tid] = cospif((float)tid * (1.0f / 32.0f));   // exact twiddles

    const float* xb = x + ((long long)b * T_DIM + (T_DIM - K_FFT)) * D_DIM + d0;
    #pragma unroll
    for (int i = 0; i < 16; i++) {
        int idx = tid + i * 256;
        int k = idx >> 6, dl = idx & 63;
        w_sh[idx] = xb[(long long)k * D_DIM + dl];
    }
    __syncthreads();

    // f[dl][n] = mix_w/64 * ( g0 + 2*sum_{f=1..31} g_f cos(2 pi f n/64) + g32*(-1)^n )
    #pragma unroll
    for (int i = 0; i < 16; i++) {
        int idx = tid + i * 256;
        int dl = idx >> 6, n = idx & 63;
        const float* gd = g_sh + dl * F_DIM;
        float s = gd[0] + gd[32] * tab[(32 * n) & 63];
        #pragma unroll
        for (int f = 1; f < 32; f++)
            s += 2.0f * gd[f] * tab[(f * n) & 63];
        f_sh[dl * 65 + n] = s * (1.0f / 64.0f) * mix_w[d0 + dl];
    }
    __syncthreads();

    const int dl = tid & 63;
    const int t0 = (tid >> 6) * 16;

    // Pre-rotated filter in registers: fr[i] = f[(t0+i)&63]
    float fr[K_FFT];
    #pragma unroll
    for (int i = 0; i < K_FFT; i++)
        fr[i] = f_sh[dl * 65 + ((t0 + i) & 63)];

    float acc[16];
    #pragma unroll
    for (int j = 0; j < 16; j++) acc[j] = 0.0f;

    #pragma unroll
    for (int k = 0; k < K_FFT; k++) {
        float wv = w_sh[k * 64 + dl];
        #pragma unroll
        for (int j = 0; j < 16; j++)
            acc[j] += wv * fr[(j - k + K_FFT) & 63];   // compile-time reg index
    }

    float* ob = out + ((long long)b * T_DIM + (T_DIM - K_FFT)) * D_DIM + d0;
    #pragma unroll
    for (int j = 0; j < 16; j++)
        ob[(long long)(t0 + j) * D_DIM + dl] = acc[j];
}

// ---------------------------------------------------------------------------
// Launch: one kernel, one graph node.
// ---------------------------------------------------------------------------
extern "C" void kernel_launch(void* const* d_in, const int* in_sizes, int n_in,
                              void* d_out, int out_size)
{
    const float* x     = (const float*)d_in[0];   // (B, T, D) fp32
    const float* mask  = (const float*)d_in[1];   // (D, 33)   fp32
    const float* mix_w = (const float*)d_in[2];   // (D,)      fp32
    float* out = (float*)d_out;                   // (B, T, D) fp32

    spectral_fused_kernel<<<GRID_TOTAL, 256>>>(x, mask, mix_w, out);
}

// round 7
// speedup vs baseline: 1.2741x; 1.0691x over previous
#include <cuda_runtime.h>
#include <cuda_bf16.h>

// Problem constants (fixed shapes from setup_inputs)
#define B_DIM 8
#define T_DIM 4096
#define D_DIM 1024
#define K_FFT 64
#define F_DIM (K_FFT / 2 + 1)        // 33

#define NUM_CONV 128                            // B * D/64
#define GRID_TOTAL  592                         // 4 blocks/SM * 148 SMs: one exact wave
#define NUM_ZERO (GRID_TOTAL - NUM_CONV)        // 464

// Zero region: rows [0, T-K) of each batch, as float4.
#define Z4_PER_B   ((T_DIM - K_FFT) * D_DIM / 4)   // 1,032,192 float4 per batch
#define Z4_TOTAL   (Z4_PER_B * B_DIM)               // 8,257,536
#define BSTRIDE4   (T_DIM * D_DIM / 4)              // 4,194,304
// Conv blocks join the fill late (~5us of ~27us); give them ~17.5% of the work.
#define SPLIT4     6815744                           // zero blocks: [0, SPLIT4)

__global__ void __launch_bounds__(256, 4) spectral_fused_kernel(
    const float* __restrict__ x, const float* __restrict__ mask,
    const float* __restrict__ mix_w, float* __restrict__ out)
{
    __shared__ float g_sh[64 * F_DIM];        // sigmoid(mask) tile [dl][f]
    __shared__ float tab[K_FFT];              // cos(2*pi*n/64)
    __shared__ float w_sh[K_FFT * 64];        // window [k][dl]
    __shared__ float f_sh[64 * (K_FFT + 1)];  // filter [dl][n], pad 65

    const int bid = blockIdx.x;
    const int tid = threadIdx.x;
    const float4 zf4 = make_float4(0.f, 0.f, 0.f, 0.f);
    float4* __restrict__ o4 = (float4*)out;

    if (bid >= NUM_CONV) {
        // ---- zero path: front 82.5% of the zero region ----
        const int stride = NUM_ZERO * 256;                 // 118,784
        for (int i = (bid - NUM_CONV) * 256 + tid; i < SPLIT4; i += stride) {
            int b   = i / Z4_PER_B;                        // const-div -> mulhi
            int off = i - b * Z4_PER_B;
            __stcs(&o4[b * BSTRIDE4 + off], zf4);
        }
        return;
    }

    // ---- conv path ----
    const int b  = bid >> 4;          // 0..7
    const int d0 = (bid & 15) * 64;   // channel tile base

    const float* mrow = mask + (long long)d0 * F_DIM;
    for (int idx = tid; idx < 64 * F_DIM; idx += 256)
        g_sh[idx] = 1.0f / (1.0f + expf(-mrow[idx]));
    if (tid < K_FFT)
        tab[tid] = cospif((float)tid * (1.0f / 32.0f));   // exact twiddles

    const float* xb = x + ((long long)b * T_DIM + (T_DIM - K_FFT)) * D_DIM + d0;
    #pragma unroll
    for (int i = 0; i < 16; i++) {
        int idx = tid + i * 256;
        int k = idx >> 6, dl = idx & 63;
        w_sh[idx] = xb[(long long)k * D_DIM + dl];
    }
    __syncthreads();

    // f[dl][n] = mix_w/64 * ( g0 + 2*sum_{f=1..31} g_f cos(2 pi f n/64) + g32*(-1)^n )
    #pragma unroll
    for (int i = 0; i < 16; i++) {
        int idx = tid + i * 256;
        int dl = idx >> 6, n = idx & 63;
        const float* gd = g_sh + dl * F_DIM;
        float s = gd[0] + gd[32] * tab[(32 * n) & 63];
        #pragma unroll
        for (int f = 1; f < 32; f++)
            s += 2.0f * gd[f] * tab[(f * n) & 63];
        f_sh[dl * 65 + n] = s * (1.0f / 64.0f) * mix_w[d0 + dl];
    }
    __syncthreads();

    const int dl = tid & 63;
    const int t0 = (tid >> 6) * 16;

    // Pre-rotated filter in registers: fr[i] = f[(t0+i)&63]
    float fr[K_FFT];
    #pragma unroll
    for (int i = 0; i < K_FFT; i++)
        fr[i] = f_sh[dl * 65 + ((t0 + i) & 63)];

    float acc[16];
    #pragma unroll
    for (int j = 0; j < 16; j++) acc[j] = 0.0f;

    #pragma unroll
    for (int k = 0; k < K_FFT; k++) {
        float wv = w_sh[k * 64 + dl];
        #pragma unroll
        for (int j = 0; j < 16; j++)
            acc[j] += wv * fr[(j - k + K_FFT) & 63];   // compile-time reg index
    }

    float* ob = out + ((long long)b * T_DIM + (T_DIM - K_FFT)) * D_DIM + d0;
    #pragma unroll
    for (int j = 0; j < 16; j++)
        ob[(long long)(t0 + j) * D_DIM + dl] = acc[j];

    // ---- conv blocks join the zero-fill: back 17.5% of the region ----
    {
        const int stride = NUM_CONV * 256;                 // 32,768
        for (int i = SPLIT4 + bid * 256 + tid; i < Z4_TOTAL; i += stride) {
            int bb  = i / Z4_PER_B;
            int off = i - bb * Z4_PER_B;
            __stcs(&o4[bb * BSTRIDE4 + off], zf4);
        }
    }
}

// ---------------------------------------------------------------------------
// Launch: one kernel, one graph node.
// ---------------------------------------------------------------------------
extern "C" void kernel_launch(void* const* d_in, const int* in_sizes, int n_in,
                              void* d_out, int out_size)
{
    const float* x     = (const float*)d_in[0];   // (B, T, D) fp32
    const float* mask  = (const float*)d_in[1];   // (D, 33)   fp32
    const float* mix_w = (const float*)d_in[2];   // (D,)      fp32
    float* out = (float*)d_out;                   // (B, T, D) fp32

    spectral_fused_kernel<<<GRID_TOTAL, 256>>>(x, mask, mix_w, out);
}